// round 14
// baseline (speedup 1.0000x reference)
#include <cuda_runtime.h>
#include <cuda_bf16.h>
#include <cuda_fp16.h>
#include <math.h>
#include <stdint.h>

// Problem constants.
#define NB 4096
#define ND 512
#define TS 127           // tile stride (rows AND cols); tile extent 128
#define NT 33            // tiles per dimension
#define NBLK (NT * (NT + 1) / 2)   // 561 upper-triangle tiles

// SMEM: 2 stages x (A 18432 + B 18432) = 73728, then small arrays.
#define STAGE_BYTES 36864
#define OFF_A(s)  ((s) * STAGE_BYTES)
#define OFF_B(s)  (OFF_A(s) + 18432)
#define OFF_CBL   73728                     // 128 f32 col cBL (x1024)
#define OFF_CBE   74240                     // 128 f32 col cBE
#define OFF_BNDM  74752                     // 128 f32 (col-64 mL boundary)
#define OFF_BNDD  75264                     // 128 f32 (col-64 dE boundary)
#define OFF_CBLR  75776                     // 128 f32 row cBL (x1024)
#define OFF_CBER  76288                     // 128 f32 row cBE
#define OFF_RAEC  76800                     // 128 f32 col rAE
#define OFF_ROWM  77312                     // 4x128 f32 mirror boundary mL
#define OFF_ROWD  79360                     // 4x128 f32 mirror boundary dE
#define OFF_WS    81408                     // 8 f32 warp sums
#define SMEM_TOTAL 81440
#define ROWB 144

// FP8 scale: low rows stored as e4m3 of (x * 32); Gram scales by 1024.
#define F8_SCALE 32.0f
#define F8_SQ    1024.0f

// Scratch (__device__ globals; no allocation anywhere).
__device__ __align__(16) uint8_t g_lowF8[NB * ND];
__device__ __align__(16) __half  g_embH[NB * ND];
__device__ float  g_cBL[NB], g_cBE[NB], g_rAE[NB];
__device__ double g_part[NBLK];

// ---------------------------------------------------------------------------
// PTX helpers (plain compute_103-legal: cp.async, ldmatrix, legacy mma only).
// ---------------------------------------------------------------------------
__device__ __forceinline__ uint32_t smem_u32(const void* p) {
    uint32_t a;
    asm("{ .reg .u64 t; cvta.to.shared.u64 t, %1; cvt.u32.u64 %0, t; }" : "=r"(a) : "l"(p));
    return a;
}
__device__ __forceinline__ void cp16(uint32_t dst, const void* src) {
    asm volatile("{ .reg .u64 g; cvta.to.global.u64 g, %1;"
                 " cp.async.cg.shared.global [%0], [g], 16; }"
                 :: "r"(dst), "l"(src) : "memory");
}
#define CP_COMMIT() asm volatile("cp.async.commit_group;" ::: "memory")
#define CP_WAIT(n)  asm volatile("cp.async.wait_group " #n ";" ::: "memory")

__device__ __forceinline__ void ldsm4(uint32_t& r0, uint32_t& r1, uint32_t& r2,
                                      uint32_t& r3, uint32_t addr) {
    asm volatile("ldmatrix.sync.aligned.m8n8.x4.shared.b16 {%0,%1,%2,%3}, [%4];"
                 : "=r"(r0), "=r"(r1), "=r"(r2), "=r"(r3) : "r"(addr));
}
// f16-accumulate MMAs: D/C are 2 regs of f16x2.
__device__ __forceinline__ void mma_f16_h(uint32_t* d, const uint32_t* a,
                                          uint32_t b0, uint32_t b1) {
    asm volatile("mma.sync.aligned.m16n8k16.row.col.f16.f16.f16.f16 "
                 "{%0,%1}, {%2,%3,%4,%5}, {%6,%7}, {%0,%1};"
                 : "+r"(d[0]), "+r"(d[1])
                 : "r"(a[0]), "r"(a[1]), "r"(a[2]), "r"(a[3]), "r"(b0), "r"(b1));
}
__device__ __forceinline__ void mma_fp8_h(uint32_t* d, const uint32_t* a,
                                          uint32_t b0, uint32_t b1) {
    asm volatile("mma.sync.aligned.m16n8k32.row.col.f16.e4m3.e4m3.f16 "
                 "{%0,%1}, {%2,%3,%4,%5}, {%6,%7}, {%0,%1};"
                 : "+r"(d[0]), "+r"(d[1])
                 : "r"(a[0]), "r"(a[1]), "r"(a[2]), "r"(a[3]), "r"(b0), "r"(b1));
}
__device__ __forceinline__ float fsqrt_fast(float x) {
    float r; asm("sqrt.approx.f32 %0, %1;" : "=f"(r) : "f"(x)); return r;
}
__device__ __forceinline__ uint16_t f8pack(float lo, float hi) {
    uint16_t p;
    asm("cvt.rn.satfinite.e4m3x2.f32 %0, %1, %2;" : "=h"(p) : "f"(hi), "f"(lo));
    return p;
}
__device__ __forceinline__ float pair_term(float m0, float m1, float d0, float d1) {
    float g = d1 - d0;
    float sgn = (m0 > m1) ? 1.f : ((m0 < m1) ? -1.f : 0.f);
    return fmaf(sgn, g, fabsf(g));
}

// One K-stage of loads (128 rows x 128 bytes each for A and B; rows clamped).
__device__ __forceinline__ void issue_stage(const uint8_t* __restrict__ g,
                                            size_t row_bytes, int r0, int c0,
                                            int kt, uint32_t aB, uint32_t bB,
                                            int tid) {
    #pragma unroll
    for (int i = 0; i < 4; ++i) {
        int c = tid + i * 256;
        int row = c >> 3, kc = c & 7;
        int gr = r0 + row; if (gr > NB - 1) gr = NB - 1;
        cp16(aB + row * ROWB + kc * 16,
             g + (size_t)gr * row_bytes + kt * 128 + kc * 16);
    }
    #pragma unroll
    for (int i = 0; i < 4; ++i) {
        int c = tid + i * 256;
        int row = c >> 3, kc = c & 7;
        int gr = c0 + row; if (gr > NB - 1) gr = NB - 1;
        cp16(bB + row * ROWB + kc * 16,
             g + (size_t)gr * row_bytes + kt * 128 + kc * 16);
    }
}

// ---------------------------------------------------------------------------
// Kernel 1: warp-per-(row,matrix) normalize; shfl-only, no smem, no syncs.
// Low -> e4m3 (x32). Embed -> f16. Coeffs in f32.
// ---------------------------------------------------------------------------
__global__ void __launch_bounds__(256) prep_kernel(const float* __restrict__ low,
                                                   const float* __restrict__ emb) {
    const int task = blockIdx.x * 8 + (threadIdx.x >> 5);   // 0..8191
    const int lane = threadIdx.x & 31;
    const int row  = task >> 1;
    const int m    = task & 1;

    const float* src = (m ? emb : low) + (size_t)row * ND;
    float4 v[4];
    #pragma unroll
    for (int i = 0; i < 4; ++i)
        v[i] = *(const float4*)(src + (lane + i * 32) * 4);

    float sum = 0.f, ssq = 0.f;
    #pragma unroll
    for (int i = 0; i < 4; ++i) {
        sum += v[i].x + v[i].y + v[i].z + v[i].w;
        ssq = fmaf(v[i].x, v[i].x, fmaf(v[i].y, v[i].y,
              fmaf(v[i].z, v[i].z, fmaf(v[i].w, v[i].w, ssq))));
    }
    #pragma unroll
    for (int o = 16; o; o >>= 1) {
        sum += __shfl_down_sync(0xffffffffu, sum, o);
        ssq += __shfl_down_sync(0xffffffffu, ssq, o);
    }
    float inv = 0.f;
    if (lane == 0) {
        inv = 1.0f / fmaxf(sqrtf(ssq), 1e-12f);
        float xx = ssq * inv * inv;
        float s  = sum * inv;
        if (m == 0) {
            g_cBL[row] = xx - 2e-6f * s;
        } else {
            g_rAE[row] = xx + 2e-6f * s + 5.12e-10f;
            g_cBE[row] = xx - 2e-6f * s;
        }
    }
    inv = __shfl_sync(0xffffffffu, inv, 0);

    if (m == 0) {
        const float sc = inv * F8_SCALE;
        #pragma unroll
        for (int i = 0; i < 4; ++i) {
            uint32_t packed = (uint32_t)f8pack(v[i].x * sc, v[i].y * sc)
                            | ((uint32_t)f8pack(v[i].z * sc, v[i].w * sc) << 16);
            *(uint32_t*)(g_lowF8 + (size_t)row * ND + (lane + i * 32) * 4) = packed;
        }
    } else {
        #pragma unroll
        for (int i = 0; i < 4; ++i) {
            __half2 h0 = __floats2half2_rn(v[i].x * inv, v[i].y * inv);
            __half2 h1 = __floats2half2_rn(v[i].z * inv, v[i].w * inv);
            uint2 u; u.x = *(uint32_t*)&h0; u.y = *(uint32_t*)&h1;
            *(uint2*)(g_embH + (size_t)row * ND + (lane + i * 32) * 4) = u;
        }
    }
}

// ---------------------------------------------------------------------------
// Kernel 2: symmetric upper-triangle tiling; single-sync double-buffered
// mainloop (12 barriers); off-diagonal tiles emit normal + mirrored terms.
// ---------------------------------------------------------------------------
__global__ void __launch_bounds__(256, 2) main_kernel() {
    extern __shared__ __align__(16) char smem[];
    const uint32_t sb = smem_u32(smem);
    const int tid = threadIdx.x;
    const int wid = tid >> 5, lane = tid & 31;
    const int q = lane & 3, R = lane >> 2;

    // Decode upper-triangle pair (a <= b) from linear index.
    int idx = blockIdx.x;
    int b = (int)((sqrtf(8.f * idx + 1.f) - 1.f) * 0.5f);
    while ((b + 1) * (b + 2) / 2 <= idx) ++b;
    while (b * (b + 1) / 2 > idx) --b;
    const int a = idx - b * (b + 1) / 2;
    const int r0 = a * TS;
    const int c0 = b * TS;

    // Stage coefficient arrays.
    if (tid < 128) {
        int gj = c0 + tid; if (gj > NB - 1) gj = NB - 1;
        int gi = r0 + tid; if (gi > NB - 1) gi = NB - 1;
        *(float*)(smem + OFF_CBL  + tid * 4) = g_cBL[gj] * F8_SQ;
        *(float*)(smem + OFF_CBE  + tid * 4) = g_cBE[gj];
        *(float*)(smem + OFF_CBLR + tid * 4) = g_cBL[gi] * F8_SQ;
        *(float*)(smem + OFF_CBER + tid * 4) = g_cBE[gi];
        *(float*)(smem + OFF_RAEC + tid * 4) = g_rAE[gj];
    }

    // Warp tile: 32 rows x 64 cols. Warp grid 4 (rows) x 2 (cols).
    const int wr0 = (wid & 3) * 32;
    const int wc0 = (wid >> 2) * 64;

    const int a_row  = ((lane >> 3) & 1) * 8 + (lane & 7);
    const int a_kofB = (lane >> 4) * 16;
    const int b_n    = (lane >> 4) * 8 + (lane & 7);
    const int b_kofB = ((lane >> 3) & 1) * 16;

    uint32_t accL[2][8][2];
    uint32_t accE[2][8][2];

    issue_stage(g_lowF8, ND, r0, c0, 0, sb + OFF_A(0), sb + OFF_B(0), tid);
    CP_COMMIT();

    // Single-sync double-buffered mainloop. Barrier at loop top proves every
    // warp finished reading the buffer the upcoming issue overwrites (that
    // buffer was last read in iteration kt-1, before this barrier).
    #pragma unroll
    for (int pass = 0; pass < 2; ++pass) {
        const uint8_t* gcur = pass ? (const uint8_t*)g_embH : g_lowF8;
        const size_t rb = pass ? (size_t)ND * 2 : (size_t)ND;
        const int NK = pass ? 8 : 4;
        uint32_t (*acc)[8][2] = pass ? accE : accL;
        #pragma unroll
        for (int mt = 0; mt < 2; ++mt)
            #pragma unroll
            for (int nt = 0; nt < 8; ++nt) { acc[mt][nt][0] = 0u; acc[mt][nt][1] = 0u; }

        for (int kt = 0; kt < NK; ++kt) {
            CP_WAIT(0);
            __syncthreads();
            if (kt < NK - 1) {
                issue_stage(gcur, rb, r0, c0, kt + 1,
                            sb + OFF_A((kt + 1) & 1), sb + OFF_B((kt + 1) & 1), tid);
                CP_COMMIT();
            } else if (pass == 0) {
                // NK=4: pass-0 ends on parity 1; embed kt0 targets stage 0.
                issue_stage((const uint8_t*)g_embH, (size_t)ND * 2, r0, c0, 0,
                            sb + OFF_A(0), sb + OFF_B(0), tid);
                CP_COMMIT();
            }

            const uint32_t aBase = sb + OFF_A(kt & 1);
            const uint32_t bBase = sb + OFF_B(kt & 1);
            #pragma unroll
            for (int ks = 0; ks < 4; ++ks) {
                uint32_t afr[2][4];
                #pragma unroll
                for (int mt = 0; mt < 2; ++mt)
                    ldsm4(afr[mt][0], afr[mt][1], afr[mt][2], afr[mt][3],
                          aBase + (wr0 + 16 * mt + a_row) * ROWB + ks * 32 + a_kofB);
                #pragma unroll
                for (int nt2 = 0; nt2 < 4; ++nt2) {
                    uint32_t b0, b1, b2, b3;
                    ldsm4(b0, b1, b2, b3,
                          bBase + (wc0 + 16 * nt2 + b_n) * ROWB + ks * 32 + b_kofB);
                    #pragma unroll
                    for (int mt = 0; mt < 2; ++mt) {
                        if (pass == 0) {
                            mma_fp8_h(acc[mt][nt2 * 2],     afr[mt], b0, b1);
                            mma_fp8_h(acc[mt][nt2 * 2 + 1], afr[mt], b2, b3);
                        } else {
                            mma_f16_h(acc[mt][nt2 * 2],     afr[mt], b0, b1);
                            mma_f16_h(acc[mt][nt2 * 2 + 1], afr[mt], b2, b3);
                        }
                    }
                }
            }
        }
    }

    const float* sCBL  = (const float*)(smem + OFF_CBL);
    const float* sCBE  = (const float*)(smem + OFF_CBE);
    const float* cBLr  = (const float*)(smem + OFF_CBLR);
    const float* cBEr  = (const float*)(smem + OFF_CBER);
    const float* rAEc  = (const float*)(smem + OFF_RAEC);
    float* bndM = (float*)(smem + OFF_BNDM);
    float* bndD = (float*)(smem + OFF_BNDD);
    float* rowM = (float*)(smem + OFF_ROWM);
    float* rowD = (float*)(smem + OFF_ROWD);

    // Barrier: mainloop's last compute reads stage SMEM; boundary publishes
    // below write non-overlapping regions, but emission reads cross-warp data.
    __syncthreads();

    // Normal boundary: wc0==64 group, q==0 owns col 64.
    if (wc0 == 64 && q == 0) {
        #pragma unroll
        for (int mt = 0; mt < 2; ++mt)
            #pragma unroll
            for (int h = 0; h < 2; ++h) {
                int rr = wr0 + 16 * mt + 8 * h + R;
                float2 l = __half22float2(*(__half2*)&accL[mt][0][h]);
                float2 e = __half22float2(*(__half2*)&accE[mt][0][h]);
                bndM[rr] = sCBL[64] - 2.f * l.x;
                int gi = r0 + rr; if (gi > NB - 1) gi = NB - 1;
                float sq = g_rAE[gi] + sCBE[64] - 2.f * e.x;
                bndD[rr] = fsqrt_fast(fmaxf(sq, 0.f));
            }
    }
    // Mirror boundary: warps wr0 in {32,64,96}, lanes 0..3 publish s=0,R=0 row.
    if ((wid & 3) != 0 && lane < 4) {
        int wg = (wid & 3) - 1;
        #pragma unroll
        for (int nt = 0; nt < 8; ++nt) {
            int cc = wc0 + 8 * nt + 2 * lane;
            float2 l = __half22float2(*(__half2*)&accL[0][nt][0]);
            float2 e = __half22float2(*(__half2*)&accE[0][nt][0]);
            rowM[wg * 128 + cc]     = cBLr[wr0] - 2.f * l.x;
            rowM[wg * 128 + cc + 1] = cBLr[wr0] - 2.f * l.y;
            rowD[wg * 128 + cc]     = fsqrt_fast(fmaxf(rAEc[cc]     + cBEr[wr0] - 2.f * e.x, 0.f));
            rowD[wg * 128 + cc + 1] = fsqrt_fast(fmaxf(rAEc[cc + 1] + cBEr[wr0] - 2.f * e.y, 0.f));
        }
    }
    __syncthreads();

    float partial = 0.f;

    // ---- Normal (column-pair) emission ----
    #pragma unroll
    for (int mt = 0; mt < 2; ++mt) {
        #pragma unroll
        for (int h = 0; h < 2; ++h) {
            const int rr = wr0 + 16 * mt + 8 * h + R;
            const int gi = r0 + rr;
            const bool rok = (gi <= NB - 2) && (rr < 127);
            int giC = gi > NB - 1 ? NB - 1 : gi;
            const float rA = g_rAE[giC];
            float mA[8], mB[8], dA[8], dB[8];
            #pragma unroll
            for (int nt = 0; nt < 8; ++nt) {
                const int cc = wc0 + 8 * nt + 2 * q;
                float2 l = __half22float2(*(__half2*)&accL[mt][nt][h]);
                float2 e = __half22float2(*(__half2*)&accE[mt][nt][h]);
                mA[nt] = sCBL[cc] - 2.f * l.x;
                mB[nt] = sCBL[cc + 1] - 2.f * l.y;
                dA[nt] = fsqrt_fast(fmaxf(rA + sCBE[cc] - 2.f * e.x, 0.f));
                dB[nt] = fsqrt_fast(fmaxf(rA + sCBE[cc + 1] - 2.f * e.y, 0.f));
            }
            const float bM = bndM[rr], bD = bndD[rr];
            #pragma unroll
            for (int nt = 0; nt < 8; ++nt) {
                {
                    int t = wc0 + 8 * nt + 2 * q;
                    if (rok && (c0 + t) <= NB - 3)
                        partial += pair_term(mA[nt], mB[nt], dA[nt], dB[nt]);
                }
                float dnM = __shfl_down_sync(0xffffffffu, mA[nt], 1);
                float dnD = __shfl_down_sync(0xffffffffu, dA[nt], 1);
                float upM = __shfl_sync(0xffffffffu, (nt < 7) ? mA[nt + 1] : 0.f, lane & ~3);
                float upD = __shfl_sync(0xffffffffu, (nt < 7) ? dA[nt + 1] : 0.f, lane & ~3);
                float nxM = (q < 3) ? dnM : ((nt < 7) ? upM : bM);
                float nxD = (q < 3) ? dnD : ((nt < 7) ? upD : bD);
                int t = wc0 + 8 * nt + 2 * q + 1;
                if (rok && t < 127 && (c0 + t) <= NB - 3)
                    partial += pair_term(mB[nt], nxM, dB[nt], nxD);
            }
        }
    }

    // ---- Mirrored (row-pair) emission: off-diagonal tiles only ----
    if (a < b) {
        const int wg = wid & 3;
        #pragma unroll
        for (int nt = 0; nt < 8; ++nt) {
            const int ccA = wc0 + 8 * nt + 2 * q;
            const int ccB = ccA + 1;
            const float rAEa = rAEc[ccA], rAEb = rAEc[ccB];
            float mA[4], mB[4], dA[4], dB[4];
            #pragma unroll
            for (int s = 0; s < 4; ++s) {
                const int rl = wr0 + 8 * s + R;
                float2 l = __half22float2(*(__half2*)&accL[s >> 1][nt][s & 1]);
                float2 e = __half22float2(*(__half2*)&accE[s >> 1][nt][s & 1]);
                mA[s] = cBLr[rl] - 2.f * l.x;
                mB[s] = cBLr[rl] - 2.f * l.y;
                dA[s] = fsqrt_fast(fmaxf(rAEa + cBEr[rl] - 2.f * e.x, 0.f));
                dB[s] = fsqrt_fast(fmaxf(rAEb + cBEr[rl] - 2.f * e.y, 0.f));
            }
            #pragma unroll
            for (int s = 0; s < 4; ++s) {
                const int rl = wr0 + 8 * s + R;
                float dnMA = __shfl_down_sync(0xffffffffu, mA[s], 4);
                float dnMB = __shfl_down_sync(0xffffffffu, mB[s], 4);
                float dnDA = __shfl_down_sync(0xffffffffu, dA[s], 4);
                float dnDB = __shfl_down_sync(0xffffffffu, dB[s], 4);
                int s1 = (s < 3) ? s + 1 : 3;
                float slMA = __shfl_sync(0xffffffffu, mA[s1], q);
                float slMB = __shfl_sync(0xffffffffu, mB[s1], q);
                float slDA = __shfl_sync(0xffffffffu, dA[s1], q);
                float slDB = __shfl_sync(0xffffffffu, dB[s1], q);
                float nMA = (R < 7) ? dnMA : ((s < 3) ? slMA : rowM[((wg < 3) ? wg : 0) * 128 + ccA]);
                float nMB = (R < 7) ? dnMB : ((s < 3) ? slMB : rowM[((wg < 3) ? wg : 0) * 128 + ccB]);
                float nDA = (R < 7) ? dnDA : ((s < 3) ? slDA : rowD[((wg < 3) ? wg : 0) * 128 + ccA]);
                float nDB = (R < 7) ? dnDB : ((s < 3) ? slDB : rowD[((wg < 3) ? wg : 0) * 128 + ccB]);
                bool rvalid = (rl < 127) && ((r0 + rl) <= NB - 3);
                if (rvalid && ccA < 127 && (c0 + ccA) <= NB - 2)
                    partial += pair_term(mA[s], nMA, dA[s], nDA);
                if (rvalid && ccB < 127 && (c0 + ccB) <= NB - 2)
                    partial += pair_term(mB[s], nMB, dB[s], nDB);
            }
        }
    }

    // Reduce to per-block partial.
    #pragma unroll
    for (int o = 16; o; o >>= 1)
        partial += __shfl_down_sync(0xffffffffu, partial, o);
    if (lane == 0) *(float*)(smem + OFF_WS + wid * 4) = partial;
    __syncthreads();
    if (tid == 0) {
        float bsum = 0.f;
        #pragma unroll
        for (int w = 0; w < 8; ++w) bsum += *(float*)(smem + OFF_WS + w * 4);
        g_part[blockIdx.x] = (double)bsum;
    }
}

// ---------------------------------------------------------------------------
// Kernel 3: deterministic fixed-order final reduction.
// ---------------------------------------------------------------------------
__global__ void reduce_kernel(float* __restrict__ out) {
    __shared__ double sm[256];
    double s = 0.0;
    for (int idx = threadIdx.x; idx < NBLK; idx += 256) s += g_part[idx];
    sm[threadIdx.x] = s;
    __syncthreads();
    for (int o = 128; o; o >>= 1) {
        if (threadIdx.x < o) sm[threadIdx.x] += sm[threadIdx.x + o];
        __syncthreads();
    }
    if (threadIdx.x == 0)
        out[0] = (float)(sm[0] / ((double)(NB - 1) * (double)(NB - 2)));
}

extern "C" void kernel_launch(void* const* d_in, const int* in_sizes, int n_in,
                              void* d_out, int out_size) {
    const float* low = (const float*)d_in[0];
    const float* emb = (const float*)d_in[1];
    float* out = (float*)d_out;

    cudaFuncSetAttribute(main_kernel, cudaFuncAttributeMaxDynamicSharedMemorySize,
                         SMEM_TOTAL);
    prep_kernel<<<1024, 256>>>(low, emb);
    main_kernel<<<NBLK, 256, SMEM_TOTAL>>>();
    reduce_kernel<<<1, 256>>>(out);
}

// round 15
// speedup vs baseline: 1.0157x; 1.0157x over previous
#include <cuda_runtime.h>
#include <cuda_bf16.h>
#include <cuda_fp16.h>
#include <math.h>
#include <stdint.h>

// Problem constants.
#define NB 4096
#define ND 512
#define TS 127           // tile stride (rows AND cols); tile extent 128
#define NT 33            // tiles per dimension
#define NBLK (NT * (NT + 1) / 2)   // 561 upper-triangle tiles

// SMEM: 2 stages x (A 18432 + B 18432) = 73728, then small arrays.
#define STAGE_BYTES 36864
#define OFF_A(s)  ((s) * STAGE_BYTES)
#define OFF_B(s)  (OFF_A(s) + 18432)
#define OFF_CBL   73728                     // 128 f32 col cBL (x1024)
#define OFF_CBE   74240                     // 128 f32 col cBE
#define OFF_BNDM  74752                     // 128 f32 (col-64 mL boundary)
#define OFF_BNDD  75264                     // 128 f32 (col-64 dE boundary)
#define OFF_CBLR  75776                     // 128 f32 row cBL (x1024)
#define OFF_CBER  76288                     // 128 f32 row cBE
#define OFF_RAEC  76800                     // 128 f32 col rAE
#define OFF_ROWM  77312                     // 4x128 f32 mirror boundary mL
#define OFF_ROWD  79360                     // 4x128 f32 mirror boundary dE
#define OFF_WS    81408                     // 8 f32 warp sums
#define SMEM_TOTAL 81440
#define ROWB 144

// FP8 scale: low rows stored as e4m3 of (x * 32); Gram scales by 1024.
#define F8_SCALE 32.0f
#define F8_SQ    1024.0f

// Scratch (__device__ globals; no allocation anywhere).
__device__ __align__(16) uint8_t g_lowF8[NB * ND];
__device__ __align__(16) __half  g_embH[NB * ND];
__device__ float  g_cBL[NB], g_cBE[NB], g_rAE[NB];
__device__ double g_part[NBLK];

// ---------------------------------------------------------------------------
// PTX helpers (plain compute_103-legal: cp.async, ldmatrix, legacy mma only).
// ---------------------------------------------------------------------------
__device__ __forceinline__ uint32_t smem_u32(const void* p) {
    uint32_t a;
    asm("{ .reg .u64 t; cvta.to.shared.u64 t, %1; cvt.u32.u64 %0, t; }" : "=r"(a) : "l"(p));
    return a;
}
__device__ __forceinline__ void cp16(uint32_t dst, const void* src) {
    asm volatile("{ .reg .u64 g; cvta.to.global.u64 g, %1;"
                 " cp.async.cg.shared.global [%0], [g], 16; }"
                 :: "r"(dst), "l"(src) : "memory");
}
#define CP_COMMIT() asm volatile("cp.async.commit_group;" ::: "memory")
#define CP_WAIT(n)  asm volatile("cp.async.wait_group " #n ";" ::: "memory")

__device__ __forceinline__ void ldsm4(uint32_t& r0, uint32_t& r1, uint32_t& r2,
                                      uint32_t& r3, uint32_t addr) {
    asm volatile("ldmatrix.sync.aligned.m8n8.x4.shared.b16 {%0,%1,%2,%3}, [%4];"
                 : "=r"(r0), "=r"(r1), "=r"(r2), "=r"(r3) : "r"(addr));
}
// f16-accumulate MMAs: D/C are 2 regs of f16x2.
__device__ __forceinline__ void mma_f16_h(uint32_t* d, const uint32_t* a,
                                          uint32_t b0, uint32_t b1) {
    asm volatile("mma.sync.aligned.m16n8k16.row.col.f16.f16.f16.f16 "
                 "{%0,%1}, {%2,%3,%4,%5}, {%6,%7}, {%0,%1};"
                 : "+r"(d[0]), "+r"(d[1])
                 : "r"(a[0]), "r"(a[1]), "r"(a[2]), "r"(a[3]), "r"(b0), "r"(b1));
}
__device__ __forceinline__ void mma_fp8_h(uint32_t* d, const uint32_t* a,
                                          uint32_t b0, uint32_t b1) {
    asm volatile("mma.sync.aligned.m16n8k32.row.col.f16.e4m3.e4m3.f16 "
                 "{%0,%1}, {%2,%3,%4,%5}, {%6,%7}, {%0,%1};"
                 : "+r"(d[0]), "+r"(d[1])
                 : "r"(a[0]), "r"(a[1]), "r"(a[2]), "r"(a[3]), "r"(b0), "r"(b1));
}
__device__ __forceinline__ float fsqrt_fast(float x) {
    float r; asm("sqrt.approx.f32 %0, %1;" : "=f"(r) : "f"(x)); return r;
}
__device__ __forceinline__ uint16_t f8pack(float lo, float hi) {
    uint16_t p;
    asm("cvt.rn.satfinite.e4m3x2.f32 %0, %1, %2;" : "=h"(p) : "f"(hi), "f"(lo));
    return p;
}
__device__ __forceinline__ float pair_term(float m0, float m1, float d0, float d1) {
    float g = d1 - d0;
    float sgn = (m0 > m1) ? 1.f : ((m0 < m1) ? -1.f : 0.f);
    return fmaf(sgn, g, fabsf(g));
}

// One K-stage of loads (128 rows x 128 bytes each for A and B; rows clamped).
__device__ __forceinline__ void issue_stage(const uint8_t* __restrict__ g,
                                            size_t row_bytes, int r0, int c0,
                                            int kt, uint32_t aB, uint32_t bB,
                                            int tid) {
    #pragma unroll
    for (int i = 0; i < 4; ++i) {
        int c = tid + i * 256;
        int row = c >> 3, kc = c & 7;
        int gr = r0 + row; if (gr > NB - 1) gr = NB - 1;
        cp16(aB + row * ROWB + kc * 16,
             g + (size_t)gr * row_bytes + kt * 128 + kc * 16);
    }
    #pragma unroll
    for (int i = 0; i < 4; ++i) {
        int c = tid + i * 256;
        int row = c >> 3, kc = c & 7;
        int gr = c0 + row; if (gr > NB - 1) gr = NB - 1;
        cp16(bB + row * ROWB + kc * 16,
             g + (size_t)gr * row_bytes + kt * 128 + kc * 16);
    }
}

// ---------------------------------------------------------------------------
// Kernel 1: warp-per-(row,matrix) normalize; shfl-only, no smem, no syncs.
// Low -> e4m3 (x32). Embed -> f16. Coeffs in f32.
// ---------------------------------------------------------------------------
__global__ void __launch_bounds__(256) prep_kernel(const float* __restrict__ low,
                                                   const float* __restrict__ emb) {
    const int task = blockIdx.x * 8 + (threadIdx.x >> 5);   // 0..8191
    const int lane = threadIdx.x & 31;
    const int row  = task >> 1;
    const int m    = task & 1;

    const float* src = (m ? emb : low) + (size_t)row * ND;
    float4 v[4];
    #pragma unroll
    for (int i = 0; i < 4; ++i)
        v[i] = *(const float4*)(src + (lane + i * 32) * 4);

    float sum = 0.f, ssq = 0.f;
    #pragma unroll
    for (int i = 0; i < 4; ++i) {
        sum += v[i].x + v[i].y + v[i].z + v[i].w;
        ssq = fmaf(v[i].x, v[i].x, fmaf(v[i].y, v[i].y,
              fmaf(v[i].z, v[i].z, fmaf(v[i].w, v[i].w, ssq))));
    }
    #pragma unroll
    for (int o = 16; o; o >>= 1) {
        sum += __shfl_down_sync(0xffffffffu, sum, o);
        ssq += __shfl_down_sync(0xffffffffu, ssq, o);
    }
    float inv = 0.f;
    if (lane == 0) {
        inv = 1.0f / fmaxf(sqrtf(ssq), 1e-12f);
        float xx = ssq * inv * inv;
        float s  = sum * inv;
        if (m == 0) {
            g_cBL[row] = xx - 2e-6f * s;
        } else {
            g_rAE[row] = xx + 2e-6f * s + 5.12e-10f;
            g_cBE[row] = xx - 2e-6f * s;
        }
    }
    inv = __shfl_sync(0xffffffffu, inv, 0);

    if (m == 0) {
        const float sc = inv * F8_SCALE;
        #pragma unroll
        for (int i = 0; i < 4; ++i) {
            uint32_t packed = (uint32_t)f8pack(v[i].x * sc, v[i].y * sc)
                            | ((uint32_t)f8pack(v[i].z * sc, v[i].w * sc) << 16);
            *(uint32_t*)(g_lowF8 + (size_t)row * ND + (lane + i * 32) * 4) = packed;
        }
    } else {
        #pragma unroll
        for (int i = 0; i < 4; ++i) {
            __half2 h0 = __floats2half2_rn(v[i].x * inv, v[i].y * inv);
            __half2 h1 = __floats2half2_rn(v[i].z * inv, v[i].w * inv);
            uint2 u; u.x = *(uint32_t*)&h0; u.y = *(uint32_t*)&h1;
            *(uint2*)(g_embH + (size_t)row * ND + (lane + i * 32) * 4) = u;
        }
    }
}

// ---------------------------------------------------------------------------
// Kernel 2: symmetric upper-triangle tiling; single-sync double-buffered
// mainloop (12 barriers); off-diagonal tiles emit normal + mirrored terms.
// ---------------------------------------------------------------------------
__global__ void __launch_bounds__(256, 2) main_kernel() {
    extern __shared__ __align__(16) char smem[];
    const uint32_t sb = smem_u32(smem);
    const int tid = threadIdx.x;
    const int wid = tid >> 5, lane = tid & 31;
    const int q = lane & 3, R = lane >> 2;

    // Decode upper-triangle pair (a <= b) from linear index.
    int idx = blockIdx.x;
    int b = (int)((sqrtf(8.f * idx + 1.f) - 1.f) * 0.5f);
    while ((b + 1) * (b + 2) / 2 <= idx) ++b;
    while (b * (b + 1) / 2 > idx) --b;
    const int a = idx - b * (b + 1) / 2;
    const int r0 = a * TS;
    const int c0 = b * TS;

    // Stage coefficient arrays.
    if (tid < 128) {
        int gj = c0 + tid; if (gj > NB - 1) gj = NB - 1;
        int gi = r0 + tid; if (gi > NB - 1) gi = NB - 1;
        *(float*)(smem + OFF_CBL  + tid * 4) = g_cBL[gj] * F8_SQ;
        *(float*)(smem + OFF_CBE  + tid * 4) = g_cBE[gj];
        *(float*)(smem + OFF_CBLR + tid * 4) = g_cBL[gi] * F8_SQ;
        *(float*)(smem + OFF_CBER + tid * 4) = g_cBE[gi];
        *(float*)(smem + OFF_RAEC + tid * 4) = g_rAE[gj];
    }

    // Warp tile: 32 rows x 64 cols. Warp grid 4 (rows) x 2 (cols).
    const int wr0 = (wid & 3) * 32;
    const int wc0 = (wid >> 2) * 64;

    const int a_row  = ((lane >> 3) & 1) * 8 + (lane & 7);
    const int a_kofB = (lane >> 4) * 16;
    const int b_n    = (lane >> 4) * 8 + (lane & 7);
    const int b_kofB = ((lane >> 3) & 1) * 16;

    uint32_t accL[2][8][2];
    uint32_t accE[2][8][2];

    issue_stage(g_lowF8, ND, r0, c0, 0, sb + OFF_A(0), sb + OFF_B(0), tid);
    CP_COMMIT();

    // Single-sync double-buffered mainloop. Barrier at loop top proves every
    // warp finished reading the buffer the upcoming issue overwrites (that
    // buffer was last read in iteration kt-1, before this barrier).
    #pragma unroll
    for (int pass = 0; pass < 2; ++pass) {
        const uint8_t* gcur = pass ? (const uint8_t*)g_embH : g_lowF8;
        const size_t rb = pass ? (size_t)ND * 2 : (size_t)ND;
        const int NK = pass ? 8 : 4;
        uint32_t (*acc)[8][2] = pass ? accE : accL;
        #pragma unroll
        for (int mt = 0; mt < 2; ++mt)
            #pragma unroll
            for (int nt = 0; nt < 8; ++nt) { acc[mt][nt][0] = 0u; acc[mt][nt][1] = 0u; }

        for (int kt = 0; kt < NK; ++kt) {
            CP_WAIT(0);
            __syncthreads();
            if (kt < NK - 1) {
                issue_stage(gcur, rb, r0, c0, kt + 1,
                            sb + OFF_A((kt + 1) & 1), sb + OFF_B((kt + 1) & 1), tid);
                CP_COMMIT();
            } else if (pass == 0) {
                // NK=4: pass-0 ends on parity 1; embed kt0 targets stage 0.
                issue_stage((const uint8_t*)g_embH, (size_t)ND * 2, r0, c0, 0,
                            sb + OFF_A(0), sb + OFF_B(0), tid);
                CP_COMMIT();
            }

            const uint32_t aBase = sb + OFF_A(kt & 1);
            const uint32_t bBase = sb + OFF_B(kt & 1);
            #pragma unroll
            for (int ks = 0; ks < 4; ++ks) {
                uint32_t afr[2][4];
                #pragma unroll
                for (int mt = 0; mt < 2; ++mt)
                    ldsm4(afr[mt][0], afr[mt][1], afr[mt][2], afr[mt][3],
                          aBase + (wr0 + 16 * mt + a_row) * ROWB + ks * 32 + a_kofB);
                #pragma unroll
                for (int nt2 = 0; nt2 < 4; ++nt2) {
                    uint32_t b0, b1, b2, b3;
                    ldsm4(b0, b1, b2, b3,
                          bBase + (wc0 + 16 * nt2 + b_n) * ROWB + ks * 32 + b_kofB);
                    #pragma unroll
                    for (int mt = 0; mt < 2; ++mt) {
                        if (pass == 0) {
                            mma_fp8_h(acc[mt][nt2 * 2],     afr[mt], b0, b1);
                            mma_fp8_h(acc[mt][nt2 * 2 + 1], afr[mt], b2, b3);
                        } else {
                            mma_f16_h(acc[mt][nt2 * 2],     afr[mt], b0, b1);
                            mma_f16_h(acc[mt][nt2 * 2 + 1], afr[mt], b2, b3);
                        }
                    }
                }
            }
        }
    }

    const float* sCBL  = (const float*)(smem + OFF_CBL);
    const float* sCBE  = (const float*)(smem + OFF_CBE);
    const float* cBLr  = (const float*)(smem + OFF_CBLR);
    const float* cBEr  = (const float*)(smem + OFF_CBER);
    const float* rAEc  = (const float*)(smem + OFF_RAEC);
    float* bndM = (float*)(smem + OFF_BNDM);
    float* bndD = (float*)(smem + OFF_BNDD);
    float* rowM = (float*)(smem + OFF_ROWM);
    float* rowD = (float*)(smem + OFF_ROWD);

    // Barrier: mainloop's last compute reads stage SMEM; boundary publishes
    // below write non-overlapping regions, but emission reads cross-warp data.
    __syncthreads();

    // Normal boundary: wc0==64 group, q==0 owns col 64.
    if (wc0 == 64 && q == 0) {
        #pragma unroll
        for (int mt = 0; mt < 2; ++mt)
            #pragma unroll
            for (int h = 0; h < 2; ++h) {
                int rr = wr0 + 16 * mt + 8 * h + R;
                float2 l = __half22float2(*(__half2*)&accL[mt][0][h]);
                float2 e = __half22float2(*(__half2*)&accE[mt][0][h]);
                bndM[rr] = sCBL[64] - 2.f * l.x;
                int gi = r0 + rr; if (gi > NB - 1) gi = NB - 1;
                float sq = g_rAE[gi] + sCBE[64] - 2.f * e.x;
                bndD[rr] = fsqrt_fast(fmaxf(sq, 0.f));
            }
    }
    // Mirror boundary: warps wr0 in {32,64,96}, lanes 0..3 publish s=0,R=0 row.
    if ((wid & 3) != 0 && lane < 4) {
        int wg = (wid & 3) - 1;
        #pragma unroll
        for (int nt = 0; nt < 8; ++nt) {
            int cc = wc0 + 8 * nt + 2 * lane;
            float2 l = __half22float2(*(__half2*)&accL[0][nt][0]);
            float2 e = __half22float2(*(__half2*)&accE[0][nt][0]);
            rowM[wg * 128 + cc]     = cBLr[wr0] - 2.f * l.x;
            rowM[wg * 128 + cc + 1] = cBLr[wr0] - 2.f * l.y;
            rowD[wg * 128 + cc]     = fsqrt_fast(fmaxf(rAEc[cc]     + cBEr[wr0] - 2.f * e.x, 0.f));
            rowD[wg * 128 + cc + 1] = fsqrt_fast(fmaxf(rAEc[cc + 1] + cBEr[wr0] - 2.f * e.y, 0.f));
        }
    }
    __syncthreads();

    float partial = 0.f;

    // ---- Normal (column-pair) emission ----
    #pragma unroll
    for (int mt = 0; mt < 2; ++mt) {
        #pragma unroll
        for (int h = 0; h < 2; ++h) {
            const int rr = wr0 + 16 * mt + 8 * h + R;
            const int gi = r0 + rr;
            const bool rok = (gi <= NB - 2) && (rr < 127);
            int giC = gi > NB - 1 ? NB - 1 : gi;
            const float rA = g_rAE[giC];
            float mA[8], mB[8], dA[8], dB[8];
            #pragma unroll
            for (int nt = 0; nt < 8; ++nt) {
                const int cc = wc0 + 8 * nt + 2 * q;
                float2 l = __half22float2(*(__half2*)&accL[mt][nt][h]);
                float2 e = __half22float2(*(__half2*)&accE[mt][nt][h]);
                mA[nt] = sCBL[cc] - 2.f * l.x;
                mB[nt] = sCBL[cc + 1] - 2.f * l.y;
                dA[nt] = fsqrt_fast(fmaxf(rA + sCBE[cc] - 2.f * e.x, 0.f));
                dB[nt] = fsqrt_fast(fmaxf(rA + sCBE[cc + 1] - 2.f * e.y, 0.f));
            }
            const float bM = bndM[rr], bD = bndD[rr];
            #pragma unroll
            for (int nt = 0; nt < 8; ++nt) {
                {
                    int t = wc0 + 8 * nt + 2 * q;
                    if (rok && (c0 + t) <= NB - 3)
                        partial += pair_term(mA[nt], mB[nt], dA[nt], dB[nt]);
                }
                float dnM = __shfl_down_sync(0xffffffffu, mA[nt], 1);
                float dnD = __shfl_down_sync(0xffffffffu, dA[nt], 1);
                float upM = __shfl_sync(0xffffffffu, (nt < 7) ? mA[nt + 1] : 0.f, lane & ~3);
                float upD = __shfl_sync(0xffffffffu, (nt < 7) ? dA[nt + 1] : 0.f, lane & ~3);
                float nxM = (q < 3) ? dnM : ((nt < 7) ? upM : bM);
                float nxD = (q < 3) ? dnD : ((nt < 7) ? upD : bD);
                int t = wc0 + 8 * nt + 2 * q + 1;
                if (rok && t < 127 && (c0 + t) <= NB - 3)
                    partial += pair_term(mB[nt], nxM, dB[nt], nxD);
            }
        }
    }

    // ---- Mirrored (row-pair) emission: off-diagonal tiles only ----
    if (a < b) {
        const int wg = wid & 3;
        #pragma unroll
        for (int nt = 0; nt < 8; ++nt) {
            const int ccA = wc0 + 8 * nt + 2 * q;
            const int ccB = ccA + 1;
            const float rAEa = rAEc[ccA], rAEb = rAEc[ccB];
            float mA[4], mB[4], dA[4], dB[4];
            #pragma unroll
            for (int s = 0; s < 4; ++s) {
                const int rl = wr0 + 8 * s + R;
                float2 l = __half22float2(*(__half2*)&accL[s >> 1][nt][s & 1]);
                float2 e = __half22float2(*(__half2*)&accE[s >> 1][nt][s & 1]);
                mA[s] = cBLr[rl] - 2.f * l.x;
                mB[s] = cBLr[rl] - 2.f * l.y;
                dA[s] = fsqrt_fast(fmaxf(rAEa + cBEr[rl] - 2.f * e.x, 0.f));
                dB[s] = fsqrt_fast(fmaxf(rAEb + cBEr[rl] - 2.f * e.y, 0.f));
            }
            #pragma unroll
            for (int s = 0; s < 4; ++s) {
                const int rl = wr0 + 8 * s + R;
                float dnMA = __shfl_down_sync(0xffffffffu, mA[s], 4);
                float dnMB = __shfl_down_sync(0xffffffffu, mB[s], 4);
                float dnDA = __shfl_down_sync(0xffffffffu, dA[s], 4);
                float dnDB = __shfl_down_sync(0xffffffffu, dB[s], 4);
                int s1 = (s < 3) ? s + 1 : 3;
                float slMA = __shfl_sync(0xffffffffu, mA[s1], q);
                float slMB = __shfl_sync(0xffffffffu, mB[s1], q);
                float slDA = __shfl_sync(0xffffffffu, dA[s1], q);
                float slDB = __shfl_sync(0xffffffffu, dB[s1], q);
                float nMA = (R < 7) ? dnMA : ((s < 3) ? slMA : rowM[((wg < 3) ? wg : 0) * 128 + ccA]);
                float nMB = (R < 7) ? dnMB : ((s < 3) ? slMB : rowM[((wg < 3) ? wg : 0) * 128 + ccB]);
                float nDA = (R < 7) ? dnDA : ((s < 3) ? slDA : rowD[((wg < 3) ? wg : 0) * 128 + ccA]);
                float nDB = (R < 7) ? dnDB : ((s < 3) ? slDB : rowD[((wg < 3) ? wg : 0) * 128 + ccB]);
                bool rvalid = (rl < 127) && ((r0 + rl) <= NB - 3);
                if (rvalid && ccA < 127 && (c0 + ccA) <= NB - 2)
                    partial += pair_term(mA[s], nMA, dA[s], nDA);
                if (rvalid && ccB < 127 && (c0 + ccB) <= NB - 2)
                    partial += pair_term(mB[s], nMB, dB[s], nDB);
            }
        }
    }

    // Reduce to per-block partial.
    #pragma unroll
    for (int o = 16; o; o >>= 1)
        partial += __shfl_down_sync(0xffffffffu, partial, o);
    if (lane == 0) *(float*)(smem + OFF_WS + wid * 4) = partial;
    __syncthreads();
    if (tid == 0) {
        float bsum = 0.f;
        #pragma unroll
        for (int w = 0; w < 8; ++w) bsum += *(float*)(smem + OFF_WS + w * 4);
        g_part[blockIdx.x] = (double)bsum;
    }
}

// ---------------------------------------------------------------------------
// Kernel 3: deterministic fixed-order final reduction.
// ---------------------------------------------------------------------------
__global__ void reduce_kernel(float* __restrict__ out) {
    __shared__ double sm[256];
    double s = 0.0;
    for (int idx = threadIdx.x; idx < NBLK; idx += 256) s += g_part[idx];
    sm[threadIdx.x] = s;
    __syncthreads();
    for (int o = 128; o; o >>= 1) {
        if (threadIdx.x < o) sm[threadIdx.x] += sm[threadIdx.x + o];
        __syncthreads();
    }
    if (threadIdx.x == 0)
        out[0] = (float)(sm[0] / ((double)(NB - 1) * (double)(NB - 2)));
}

extern "C" void kernel_launch(void* const* d_in, const int* in_sizes, int n_in,
                              void* d_out, int out_size) {
    const float* low = (const float*)d_in[0];
    const float* emb = (const float*)d_in[1];
    float* out = (float*)d_out;

    cudaFuncSetAttribute(main_kernel, cudaFuncAttributeMaxDynamicSharedMemorySize,
                         SMEM_TOTAL);
    prep_kernel<<<1024, 256>>>(low, emb);
    main_kernel<<<NBLK, 256, SMEM_TOTAL>>>();
    reduce_kernel<<<1, 256>>>(out);
}